// round 11
// baseline (speedup 1.0000x reference)
#include <cuda_runtime.h>
#include <math.h>

// Problem constants
#define B   256
#define L   512
#define I   32
#define H   16
#define G   64            // 4*H gates
#define NT  511           // number of increments
#define SIGD 4368         // H + H^2 + H^3
#define O   10

// Scratch (device global; no allocation allowed)
static __device__ float g_xw[B * L * G];        // 33.5 MB : per-batch input projection

// ---------------------------------------------------------------------------
// Activations via hardware MUFU.TANH (lat 16).
// sigmoid(x) = 0.5*tanh(x/2) + 0.5  (exact identity; only tanh is approx)
// ---------------------------------------------------------------------------
__device__ __forceinline__ float tanh_hw(float x) {
    float y; asm("tanh.approx.f32 %0, %1;" : "=f"(y) : "f"(x)); return y;
}
__device__ __forceinline__ float sigmoid_hw(float x) {
    return fmaf(tanh_hw(0.5f * x), 0.5f, 0.5f);
}

// ---------------------------------------------------------------------------
// Packed fp32x2 helpers (Blackwell FFMA2 via PTX) — sig phase only
// ---------------------------------------------------------------------------
typedef unsigned long long u64t;
__device__ __forceinline__ u64t pack2_(float lo, float hi) {
    u64t r; asm("mov.b64 %0, {%1, %2};" : "=l"(r) : "f"(lo), "f"(hi)); return r;
}
__device__ __forceinline__ void unpack2_(u64t v, float& lo, float& hi) {
    asm("mov.b64 {%0, %1}, %2;" : "=f"(lo), "=f"(hi) : "l"(v));
}
__device__ __forceinline__ u64t ffma2_(u64t a, u64t b, u64t c) {
    u64t d; asm("fma.rn.f32x2 %0, %1, %2, %3;" : "=l"(d) : "l"(a), "l"(b), "l"(c));
    return d;
}

__device__ __forceinline__ void barA() {           // barrier for warps 0-7 only
    asm volatile("bar.sync 1, 256;" ::: "memory");
}

// ---------------------------------------------------------------------------
// FUSED + PIPELINED kernel: one block (288 thr = 9 warps) per batch element.
//   Warps 0-7: phase A (xw, 8 chunks of 64 steps, publishes s_xw_done)
//              then phase C (sig scan consuming s_d_done chunk-by-chunk + FC).
//   Warp 8:    LSTM (frozen R5 body), consuming xw chunks as they appear,
//              writing increments to shared ds[], publishing every 32 steps.
// The serial LSTM chain (warp 8, highest wid -> top arbiter priority) is the
// wall; everything else hides underneath it.
// ---------------------------------------------------------------------------
__global__ void __launch_bounds__(288) fused_kernel(const float* __restrict__ X,
                                                    const float* __restrict__ Wih,
                                                    const float* __restrict__ Whh,
                                                    const float* __restrict__ bih,
                                                    const float* __restrict__ bhh,
                                                    const float* __restrict__ fcw,
                                                    const float* __restrict__ fcb,
                                                    float* __restrict__ out) {
    __shared__ __align__(16) float ds[NT * H];     // 32704 B : increments
    __shared__ __align__(16) float Xsh[64 * 33];   // 8448 B : X chunk tile
    __shared__ float Ws[32 * 65];                  // transposed W_ih [k][g]
    __shared__ float bs[64];
    __shared__ __align__(16) float hsm[2][16];
    __shared__ float red[8][O];
    __shared__ volatile int s_xw_done;             // xw chunks completed (0..8)
    __shared__ volatile int s_d_done;              // increments completed (0..511)

    int tid   = threadIdx.x;
    int batch = blockIdx.x;
    int lane  = tid & 31;
    int warp  = tid >> 5;

    float* xwb = g_xw + (size_t)batch * (L * G);

    if (tid == 0) { s_xw_done = 0; s_d_done = 0; }
    __syncthreads();

    if (warp < 8) {
        // ================= Phase A: xw (warps 0-7) =================
        for (int i = tid; i < 2048; i += 256) {    // W_ih transpose (once)
            int g = i >> 5, k = i & 31;
            Ws[k * 65 + g] = Wih[i];
        }
        if (tid < 64) bs[tid] = bih[tid] + bhh[tid];

        int tg = tid & 15;
        int tb = tid >> 4;

        for (int c = 0; c < 8; c++) {
            barA();                                // prev chunk consumed + stores fenced
            if (tid == 0 && c > 0) s_xw_done = c;  // publish chunks 0..c-1
            for (int i = tid; i < 2048; i += 256) {
                int r = i >> 5, k = i & 31;
                Xsh[r * 33 + k] = X[((size_t)batch * L + c * 64) * I + i];
            }
            barA();

            float acc[4][4];
#pragma unroll
            for (int bi = 0; bi < 4; bi++)
#pragma unroll
                for (int gi = 0; gi < 4; gi++)
                    acc[bi][gi] = bs[tg * 4 + gi];

#pragma unroll 8
            for (int k = 0; k < I; k++) {
                float xv[4], wv[4];
#pragma unroll
                for (int bi = 0; bi < 4; bi++) xv[bi] = Xsh[(tb * 4 + bi) * 33 + k];
#pragma unroll
                for (int gi = 0; gi < 4; gi++) wv[gi] = Ws[k * 65 + tg * 4 + gi];
#pragma unroll
                for (int bi = 0; bi < 4; bi++)
#pragma unroll
                    for (int gi = 0; gi < 4; gi++)
                        acc[bi][gi] = fmaf(xv[bi], wv[gi], acc[bi][gi]);
            }

#pragma unroll
            for (int bi = 0; bi < 4; bi++) {
                int row = c * 64 + tb * 4 + bi;
                float4 v = make_float4(acc[bi][0], acc[bi][1], acc[bi][2], acc[bi][3]);
                *reinterpret_cast<float4*>(xwb + (size_t)row * G + tg * 4) = v;
            }
            __threadfence_block();                 // order my stores before publish
        }
        barA();
        if (tid == 0) s_xw_done = 8;

        // ================= Phase C: sig scan (consume s_d_done) ============
        int a  = tid >> 4;
        int bb = tid & 15;

        float S1h = 0.f, S2 = 0.f;                 // S1h = S1/2 (exact scaling)
        u64t S3p[8];
#pragma unroll
        for (int j = 0; j < 8; j++) S3p[j] = 0ull;

        for (int c = 0; c < 16; c++) {
            int tend = (c < 15) ? (c + 1) * 32 : NT;
            while (s_d_done < tend) __nanosleep(128);
            __threadfence_block();                 // acquire ds writes

#pragma unroll 2
            for (int t = c * 32; t < tend; t++) {
                const float* dr = ds + t * H;
                ulonglong2 p0 = *reinterpret_cast<const ulonglong2*>(dr);
                ulonglong2 p1 = *reinterpret_cast<const ulonglong2*>(dr + 4);
                ulonglong2 p2 = *reinterpret_cast<const ulonglong2*>(dr + 8);
                ulonglong2 p3 = *reinterpret_cast<const ulonglong2*>(dr + 12);
                float da = dr[a];
                float db = dr[bb];

                float m1   = da * db;
                float db2  = db + db;
                float coef = fmaf(S1h, db, fmaf(m1, (1.f / 6.f), S2));
                u64t cp = pack2_(coef, coef);

                S3p[0] = ffma2_(cp, p0.x, S3p[0]);
                S3p[1] = ffma2_(cp, p0.y, S3p[1]);
                S3p[2] = ffma2_(cp, p1.x, S3p[2]);
                S3p[3] = ffma2_(cp, p1.y, S3p[3]);
                S3p[4] = ffma2_(cp, p2.x, S3p[4]);
                S3p[5] = ffma2_(cp, p2.y, S3p[5]);
                S3p[6] = ffma2_(cp, p3.x, S3p[6]);
                S3p[7] = ffma2_(cp, p3.y, S3p[7]);

                S2  = fmaf(S1h, db2, fmaf(0.5f, m1, S2));
                S1h = fmaf(0.5f, da, S1h);
            }
        }

        // ---- fused FC ----
        float S3[16];
#pragma unroll
        for (int j = 0; j < 8; j++) unpack2_(S3p[j], S3[2 * j], S3[2 * j + 1]);
        float S1 = S1h + S1h;

        float part[O];
#pragma unroll
        for (int o = 0; o < O; o++) {
            const float* wr = fcw + (size_t)o * SIGD;
            float acc = S2 * __ldg(wr + H + tid);              // level-2 term
            if (bb == 0) acc = fmaf(S1, __ldg(wr + a), acc);   // level-1 term
            const float4* w4 = reinterpret_cast<const float4*>(wr + H + H * H + tid * 16);
#pragma unroll
            for (int j = 0; j < 4; j++) {
                float4 w = __ldg(w4 + j);
                acc = fmaf(S3[4 * j + 0], w.x, acc);
                acc = fmaf(S3[4 * j + 1], w.y, acc);
                acc = fmaf(S3[4 * j + 2], w.z, acc);
                acc = fmaf(S3[4 * j + 3], w.w, acc);
            }
            part[o] = acc;
        }

#pragma unroll
        for (int off = 16; off > 0; off >>= 1)
#pragma unroll
            for (int o = 0; o < O; o++)
                part[o] += __shfl_down_sync(0xffffffffu, part[o], off);
        if (lane == 0)
#pragma unroll
            for (int o = 0; o < O; o++) red[warp][o] = part[o];
    } else {
        // ================= Warp 8: LSTM (frozen R5 body) ===================
        float w0[H], w1[H];
#pragma unroll
        for (int j = 0; j < H; j++) {
            w0[j] = __ldg(Whh + lane * H + j);
            w1[j] = __ldg(Whh + (lane + 32) * H + j);
        }
        float h[H];
#pragma unroll
        for (int j = 0; j < H; j++) h[j] = 0.f;
        float c = 0.f, hprev = 0.f;

        const float* xp = xwb + lane;

        // wait for xw chunks 0,1 (prefetch reaches step 3; chunk waits below
        // keep us 2 chunks ahead of consumption)
        while (s_xw_done < 2) __nanosleep(64);
        __threadfence_block();

        float bx0[4], bx1[4];
#pragma unroll
        for (int k = 0; k < 4; k++) { bx0[k] = xp[k * G]; bx1[k] = xp[k * G + 32]; }

        for (int t = 0; t < L; t++) {
            if ((t & 63) == 0 && t) {              // entering chunk t/64
                int need = (t >> 6) + 2; if (need > 8) need = 8;
                while (s_xw_done < need) __nanosleep(64);
                __threadfence_block();
            }

            int slot = t & 3;
            float a0 = bx0[slot], a1 = bx1[slot];
            if (t + 4 < L) { bx0[slot] = xp[(t + 4) * G]; bx1[slot] = xp[(t + 4) * G + 32]; }

            float q0 = 0.f, q1 = 0.f;
#pragma unroll
            for (int j = 0; j < 8; j++) {
                a0 = fmaf(h[j],     w0[j],     a0);
                q0 = fmaf(h[j + 8], w0[j + 8], q0);
                a1 = fmaf(h[j],     w1[j],     a1);
                q1 = fmaf(h[j + 8], w1[j + 8], q1);
            }
            a0 += q0; a1 += q1;

            float fg = __shfl_down_sync(0xffffffffu, a0, 16);
            float og = __shfl_down_sync(0xffffffffu, a1, 16);

            float si = sigmoid_hw(a0);
            float sf = sigmoid_hw(fg);
            float so = sigmoid_hw(og);
            float tg = tanh_hw(a1);
            c = fmaf(sf, c, si * tg);
            float hn = so * tanh_hw(c);

            int buf = t & 1;
            if (lane < H) {
                hsm[buf][lane] = hn;
                if (t) ds[(t - 1) * H + lane] = hn - hprev;
                hprev = hn;
            }
            __syncwarp();
#pragma unroll
            for (int j = 0; j < H; j += 4) {
                float4 v = *reinterpret_cast<const float4*>(&hsm[buf][j]);
                h[j] = v.x; h[j + 1] = v.y; h[j + 2] = v.z; h[j + 3] = v.w;
            }

            if ((t & 31) == 0 && t) {              // publish increments 0..t-1
                __threadfence_block();             // all lanes fence their STS
                __syncwarp();
                if (lane == 0) s_d_done = t;
            }
        }
        __threadfence_block();
        __syncwarp();
        if (lane == 0) s_d_done = NT;              // all 511 increments ready
    }

    __syncthreads();                               // all 9 warps
    if (tid < O) {
        float v = fcb[tid];
#pragma unroll
        for (int w = 0; w < 8; w++) v += red[w][tid];
        out[batch * O + tid] = v;
    }
}

// ---------------------------------------------------------------------------
extern "C" void kernel_launch(void* const* d_in, const int* in_sizes, int n_in,
                              void* d_out, int out_size) {
    const float* X   = (const float*)d_in[0];
    const float* Wih = (const float*)d_in[1];
    const float* Whh = (const float*)d_in[2];
    const float* bih = (const float*)d_in[3];
    const float* bhh = (const float*)d_in[4];
    const float* fcw = (const float*)d_in[5];
    const float* fcb = (const float*)d_in[6];
    float* out = (float*)d_out;

    fused_kernel<<<B, 288>>>(X, Wih, Whh, bih, bhh, fcw, fcb, out);
}

// round 12
// speedup vs baseline: 1.7578x; 1.7578x over previous
#include <cuda_runtime.h>
#include <math.h>

// Problem constants
#define B   256
#define L   512
#define I   32
#define H   16
#define G   64            // 4*H gates
#define NT  511           // number of increments
#define SIGD 4368         // H + H^2 + H^3
#define O   10

// Scratch (device global; no allocation allowed)
static __device__ float g_xw[B * L * G];        // 33.5 MB : per-batch input projection

// ---------------------------------------------------------------------------
// Activations via hardware MUFU.TANH (lat 16).
// sigmoid(x) = 0.5*tanh(x/2) + 0.5  (exact identity; only tanh is approx)
// ---------------------------------------------------------------------------
__device__ __forceinline__ float tanh_hw(float x) {
    float y; asm("tanh.approx.f32 %0, %1;" : "=f"(y) : "f"(x)); return y;
}
__device__ __forceinline__ float sigmoid_hw(float x) {
    return fmaf(tanh_hw(0.5f * x), 0.5f, 0.5f);
}

// ---------------------------------------------------------------------------
// Packed fp32x2 helpers (Blackwell FFMA2 via PTX) — sig phase only
// ---------------------------------------------------------------------------
typedef unsigned long long u64t;
__device__ __forceinline__ u64t pack2_(float lo, float hi) {
    u64t r; asm("mov.b64 %0, {%1, %2};" : "=l"(r) : "f"(lo), "f"(hi)); return r;
}
__device__ __forceinline__ void unpack2_(u64t v, float& lo, float& hi) {
    asm("mov.b64 {%0, %1}, %2;" : "=f"(lo), "=f"(hi) : "l"(v));
}
__device__ __forceinline__ u64t ffma2_(u64t a, u64t b, u64t c) {
    u64t d; asm("fma.rn.f32x2 %0, %1, %2, %3;" : "=l"(d) : "l"(a), "l"(b), "l"(c));
    return d;
}

__device__ __forceinline__ void barA() {           // barrier for warps 0-7 only
    asm volatile("bar.sync 1, 256;" ::: "memory");
}
__device__ __forceinline__ void bar_wait(int id) { // HW-blocking wait (no issue)
    asm volatile("bar.sync %0, 288;" :: "r"(id) : "memory");
}
__device__ __forceinline__ void bar_post(int id) { // non-blocking arrive
    asm volatile("bar.arrive %0, 288;" :: "r"(id) : "memory");
}

// ---------------------------------------------------------------------------
// FUSED + PIPELINED kernel: one block (288 thr = 9 warps) per batch element.
//   Phase A (warps 0-7): xw, 8 chunks of 64 steps (frozen R10 structure).
//   __syncthreads (all 9 warps).
//   Phase B (warp 8): frozen R5 LSTM body writing increments to shared ds[];
//       after each 64-step chunk: threadfence + bar.arrive(2+chunk).
//   Phase C (warps 0-7): frozen sig scan consuming chunk-by-chunk, each chunk
//       gated by bar.sync (HW-parked wait, zero issue pressure on warp 8).
// ---------------------------------------------------------------------------
__global__ void __launch_bounds__(288) fused_kernel(const float* __restrict__ X,
                                                    const float* __restrict__ Wih,
                                                    const float* __restrict__ Whh,
                                                    const float* __restrict__ bih,
                                                    const float* __restrict__ bhh,
                                                    const float* __restrict__ fcw,
                                                    const float* __restrict__ fcb,
                                                    float* __restrict__ out) {
    __shared__ __align__(16) float ds[NT * H];     // 32704 B : increments
    __shared__ __align__(16) float Xsh[64 * 33];   // 8448 B : X chunk tile
    __shared__ float Ws[32 * 65];                  // transposed W_ih [k][g]
    __shared__ float bs[64];
    __shared__ __align__(16) float hsm[2][16];
    __shared__ float red[8][O];

    int tid   = threadIdx.x;
    int batch = blockIdx.x;
    int lane  = tid & 31;
    int warp  = tid >> 5;

    float* xwb = g_xw + (size_t)batch * (L * G);

    if (warp < 8) {
        // ================= Phase A: xw (warps 0-7; frozen R10) =============
        for (int i = tid; i < 2048; i += 256) {    // W_ih transpose (once)
            int g = i >> 5, k = i & 31;
            Ws[k * 65 + g] = Wih[i];
        }
        if (tid < 64) bs[tid] = bih[tid] + bhh[tid];

        int tg = tid & 15;
        int tb = tid >> 4;

        for (int c = 0; c < 8; c++) {
            barA();
            for (int i = tid; i < 2048; i += 256) {
                int r = i >> 5, k = i & 31;
                Xsh[r * 33 + k] = X[((size_t)batch * L + c * 64) * I + i];
            }
            barA();

            float acc[4][4];
#pragma unroll
            for (int bi = 0; bi < 4; bi++)
#pragma unroll
                for (int gi = 0; gi < 4; gi++)
                    acc[bi][gi] = bs[tg * 4 + gi];

#pragma unroll 8
            for (int k = 0; k < I; k++) {
                float xv[4], wv[4];
#pragma unroll
                for (int bi = 0; bi < 4; bi++) xv[bi] = Xsh[(tb * 4 + bi) * 33 + k];
#pragma unroll
                for (int gi = 0; gi < 4; gi++) wv[gi] = Ws[k * 65 + tg * 4 + gi];
#pragma unroll
                for (int bi = 0; bi < 4; bi++)
#pragma unroll
                    for (int gi = 0; gi < 4; gi++)
                        acc[bi][gi] = fmaf(xv[bi], wv[gi], acc[bi][gi]);
            }

#pragma unroll
            for (int bi = 0; bi < 4; bi++) {
                int row = c * 64 + tb * 4 + bi;
                float4 v = make_float4(acc[bi][0], acc[bi][1], acc[bi][2], acc[bi][3]);
                *reinterpret_cast<float4*>(xwb + (size_t)row * G + tg * 4) = v;
            }
        }
    }
    __syncthreads();   // xw slice complete & visible to warp 8

    if (warp == 8) {
        // ================= Phase B: LSTM (warp 8; frozen R5 body) ==========
        float w0[H], w1[H];
#pragma unroll
        for (int j = 0; j < H; j++) {
            w0[j] = __ldg(Whh + lane * H + j);
            w1[j] = __ldg(Whh + (lane + 32) * H + j);
        }
        float h[H];
#pragma unroll
        for (int j = 0; j < H; j++) h[j] = 0.f;
        float c = 0.f, hprev = 0.f;

        const float* xp = xwb + lane;

        float bx0[4], bx1[4];
#pragma unroll
        for (int k = 0; k < 4; k++) { bx0[k] = xp[k * G]; bx1[k] = xp[k * G + 32]; }

#pragma unroll 4
        for (int t = 0; t < L; t++) {
            int slot = t & 3;
            float a0 = bx0[slot], a1 = bx1[slot];
            if (t + 4 < L) { bx0[slot] = xp[(t + 4) * G]; bx1[slot] = xp[(t + 4) * G + 32]; }

            float q0 = 0.f, q1 = 0.f;
#pragma unroll
            for (int j = 0; j < 8; j++) {
                a0 = fmaf(h[j],     w0[j],     a0);
                q0 = fmaf(h[j + 8], w0[j + 8], q0);
                a1 = fmaf(h[j],     w1[j],     a1);
                q1 = fmaf(h[j + 8], w1[j + 8], q1);
            }
            a0 += q0; a1 += q1;

            float fg = __shfl_down_sync(0xffffffffu, a0, 16);
            float og = __shfl_down_sync(0xffffffffu, a1, 16);

            float si = sigmoid_hw(a0);
            float sf = sigmoid_hw(fg);
            float so = sigmoid_hw(og);
            float tg = tanh_hw(a1);
            c = fmaf(sf, c, si * tg);
            float hn = so * tanh_hw(c);

            int buf = t & 1;
            if (lane < H) {
                hsm[buf][lane] = hn;
                if (t) ds[(t - 1) * H + lane] = hn - hprev;
                hprev = hn;
            }
            __syncwarp();
#pragma unroll
            for (int j = 0; j < H; j += 4) {
                float4 v = *reinterpret_cast<const float4*>(&hsm[buf][j]);
                h[j] = v.x; h[j + 1] = v.y; h[j + 2] = v.z; h[j + 3] = v.w;
            }

            // publish chunk (t/64 - 1) = increments [0, t) — once per 64 steps
            if ((t & 63) == 0 && t) {
                __threadfence_block();
                bar_post(1 + (t >> 6));            // ids 2..8 for chunks 0..6
            }
        }
        __threadfence_block();
        bar_post(9);                               // chunk 7 (increments ..510)
    } else {
        // ================= Phase C: sig scan (warps 0-7; frozen body) ======
        int a  = tid >> 4;
        int bb = tid & 15;

        float S1h = 0.f, S2 = 0.f;                 // S1h = S1/2 (exact scaling)
        u64t S3p[8];
#pragma unroll
        for (int j = 0; j < 8; j++) S3p[j] = 0ull;

        for (int cch = 0; cch < 8; cch++) {
            bar_wait(2 + cch);                     // HW-parked until chunk ready
            int tend = (cch < 7) ? (cch + 1) * 64 : NT;

#pragma unroll 2
            for (int t = cch * 64; t < tend; t++) {
                const float* dr = ds + t * H;
                ulonglong2 p0 = *reinterpret_cast<const ulonglong2*>(dr);
                ulonglong2 p1 = *reinterpret_cast<const ulonglong2*>(dr + 4);
                ulonglong2 p2 = *reinterpret_cast<const ulonglong2*>(dr + 8);
                ulonglong2 p3 = *reinterpret_cast<const ulonglong2*>(dr + 12);
                float da = dr[a];
                float db = dr[bb];

                float m1   = da * db;
                float db2  = db + db;
                float coef = fmaf(S1h, db, fmaf(m1, (1.f / 6.f), S2));
                u64t cp = pack2_(coef, coef);

                S3p[0] = ffma2_(cp, p0.x, S3p[0]);
                S3p[1] = ffma2_(cp, p0.y, S3p[1]);
                S3p[2] = ffma2_(cp, p1.x, S3p[2]);
                S3p[3] = ffma2_(cp, p1.y, S3p[3]);
                S3p[4] = ffma2_(cp, p2.x, S3p[4]);
                S3p[5] = ffma2_(cp, p2.y, S3p[5]);
                S3p[6] = ffma2_(cp, p3.x, S3p[6]);
                S3p[7] = ffma2_(cp, p3.y, S3p[7]);

                S2  = fmaf(S1h, db2, fmaf(0.5f, m1, S2));
                S1h = fmaf(0.5f, da, S1h);
            }
        }

        // ---- fused FC ----
        float S3[16];
#pragma unroll
        for (int j = 0; j < 8; j++) unpack2_(S3p[j], S3[2 * j], S3[2 * j + 1]);
        float S1 = S1h + S1h;

        float part[O];
#pragma unroll
        for (int o = 0; o < O; o++) {
            const float* wr = fcw + (size_t)o * SIGD;
            float acc = S2 * __ldg(wr + H + tid);              // level-2 term
            if (bb == 0) acc = fmaf(S1, __ldg(wr + a), acc);   // level-1 term
            const float4* w4 = reinterpret_cast<const float4*>(wr + H + H * H + tid * 16);
#pragma unroll
            for (int j = 0; j < 4; j++) {
                float4 w = __ldg(w4 + j);
                acc = fmaf(S3[4 * j + 0], w.x, acc);
                acc = fmaf(S3[4 * j + 1], w.y, acc);
                acc = fmaf(S3[4 * j + 2], w.z, acc);
                acc = fmaf(S3[4 * j + 3], w.w, acc);
            }
            part[o] = acc;
        }

#pragma unroll
        for (int off = 16; off > 0; off >>= 1)
#pragma unroll
            for (int o = 0; o < O; o++)
                part[o] += __shfl_down_sync(0xffffffffu, part[o], off);
        if (lane == 0)
#pragma unroll
            for (int o = 0; o < O; o++) red[warp][o] = part[o];
    }

    __syncthreads();                               // all 9 warps
    if (tid < O) {
        float v = fcb[tid];
#pragma unroll
        for (int w = 0; w < 8; w++) v += red[w][tid];
        out[batch * O + tid] = v;
    }
}

// ---------------------------------------------------------------------------
extern "C" void kernel_launch(void* const* d_in, const int* in_sizes, int n_in,
                              void* d_out, int out_size) {
    const float* X   = (const float*)d_in[0];
    const float* Wih = (const float*)d_in[1];
    const float* Whh = (const float*)d_in[2];
    const float* bih = (const float*)d_in[3];
    const float* bhh = (const float*)d_in[4];
    const float* fcw = (const float*)d_in[5];
    const float* fcb = (const float*)d_in[6];
    float* out = (float*)d_out;

    fused_kernel<<<B, 288>>>(X, Wih, Whh, bih, bhh, fcw, fcb, out);
}

// round 13
// speedup vs baseline: 1.9417x; 1.1046x over previous
#include <cuda_runtime.h>
#include <math.h>

// Problem constants
#define B   256
#define L   512
#define I   32
#define H   16
#define G   64            // 4*H gates
#define NT  511           // number of increments
#define SIGD 4368         // H + H^2 + H^3
#define O   10

// Scratch (device global; no allocation allowed)
static __device__ float g_xw[B * L * G];        // per-batch input projection
                                                // (i,f,o gate rows pre-scaled by 0.5)

// ---------------------------------------------------------------------------
// Hardware MUFU.TANH. With pre-scaled preactivations, sigmoid(x) costs just
// fma(tanh_hw(x_half), 0.5, 0.5) — no pre-multiply.
// ---------------------------------------------------------------------------
__device__ __forceinline__ float tanh_hw(float x) {
    float y; asm("tanh.approx.f32 %0, %1;" : "=f"(y) : "f"(x)); return y;
}

// ---------------------------------------------------------------------------
// Packed fp32x2 helpers (Blackwell FFMA2 via PTX) — sig phase only
// ---------------------------------------------------------------------------
typedef unsigned long long u64t;
__device__ __forceinline__ u64t pack2_(float lo, float hi) {
    u64t r; asm("mov.b64 %0, {%1, %2};" : "=l"(r) : "f"(lo), "f"(hi)); return r;
}
__device__ __forceinline__ void unpack2_(u64t v, float& lo, float& hi) {
    asm("mov.b64 {%0, %1}, %2;" : "=f"(lo), "=f"(hi) : "l"(v));
}
__device__ __forceinline__ u64t ffma2_(u64t a, u64t b, u64t c) {
    u64t d; asm("fma.rn.f32x2 %0, %1, %2, %3;" : "=l"(d) : "l"(a), "l"(b), "l"(c));
    return d;
}

__device__ __forceinline__ void barA() {           // warps 0-7 internal barrier
    asm volatile("bar.sync 1, 256;" ::: "memory");
}
__device__ __forceinline__ void bar_wait(int id) { // HW-blocking wait
    asm volatile("bar.sync %0, 288;" :: "r"(id) : "memory");
}
__device__ __forceinline__ void bar_post(int id) { // non-blocking arrive
    asm volatile("bar.arrive %0, 288;" :: "r"(id) : "memory");
}

// gate-row scale: i(0-15), f(16-31), o(48-63) -> 0.5 ; g(32-47) -> 1.0
__device__ __forceinline__ float gscale(int g) {
    return (g >= 32 && g < 48) ? 1.0f : 0.5f;
}

// ---------------------------------------------------------------------------
// FUSED + fully PIPELINED kernel: one block (288 thr = 9 warps) per batch.
//   Warps 0-7: xw in 4 chunks of 128 rows (publish ids 2-5), then sig scan
//              consuming 8 chunks of 64 steps (wait ids 6-13), then FC.
//   Warp 8:    LSTM chain (R5 body + slim 3-MUFU activations), gated on xw
//              chunks, publishing increments every 64 steps.
// ---------------------------------------------------------------------------
__global__ void __launch_bounds__(288) fused_kernel(const float* __restrict__ X,
                                                    const float* __restrict__ Wih,
                                                    const float* __restrict__ Whh,
                                                    const float* __restrict__ bih,
                                                    const float* __restrict__ bhh,
                                                    const float* __restrict__ fcw,
                                                    const float* __restrict__ fcb,
                                                    float* __restrict__ out) {
    __shared__ __align__(16) float ds[NT * H];     // 32704 B : increments
    __shared__ __align__(16) float Xsh[128 * 33];  // 16896 B : X chunk (128 rows)
    __shared__ float Ws[32 * 65];                  // transposed W_ih [k][g], scaled
    __shared__ float bs[64];                       // scaled biases
    __shared__ __align__(16) float hsm[2][16];
    __shared__ float red[8][O];

    int tid   = threadIdx.x;
    int batch = blockIdx.x;
    int lane  = tid & 31;
    int warp  = tid >> 5;

    float* xwb = g_xw + (size_t)batch * (L * G);

    if (warp < 8) {
        // ============ Phase A: xw, 4 chunks x 128 rows (warps 0-7) =========
        for (int i = tid; i < 2048; i += 256) {    // W_ih transpose + scale
            int g = i >> 5, k = i & 31;
            Ws[k * 65 + g] = Wih[i] * gscale(g);
        }
        if (tid < 64) bs[tid] = (bih[tid] + bhh[tid]) * gscale(tid);

        int tg = tid & 15;
        int tb = tid >> 4;

        for (int c = 0; c < 4; c++) {
            barA();
            for (int i = tid; i < 4096; i += 256) {
                int r = i >> 5, k = i & 31;
                Xsh[r * 33 + k] = X[((size_t)batch * L + c * 128) * I + i];
            }
            barA();

#pragma unroll
            for (int s = 0; s < 2; s++) {
                float acc[4][4];
#pragma unroll
                for (int bi = 0; bi < 4; bi++)
#pragma unroll
                    for (int gi = 0; gi < 4; gi++)
                        acc[bi][gi] = bs[tg * 4 + gi];

#pragma unroll 8
                for (int k = 0; k < I; k++) {
                    float xv[4], wv[4];
#pragma unroll
                    for (int bi = 0; bi < 4; bi++)
                        xv[bi] = Xsh[(s * 64 + tb * 4 + bi) * 33 + k];
#pragma unroll
                    for (int gi = 0; gi < 4; gi++) wv[gi] = Ws[k * 65 + tg * 4 + gi];
#pragma unroll
                    for (int bi = 0; bi < 4; bi++)
#pragma unroll
                        for (int gi = 0; gi < 4; gi++)
                            acc[bi][gi] = fmaf(xv[bi], wv[gi], acc[bi][gi]);
                }

#pragma unroll
                for (int bi = 0; bi < 4; bi++) {
                    int row = c * 128 + s * 64 + tb * 4 + bi;
                    float4 v = make_float4(acc[bi][0], acc[bi][1], acc[bi][2], acc[bi][3]);
                    *reinterpret_cast<float4*>(xwb + (size_t)row * G + tg * 4) = v;
                }
            }
            __threadfence_block();
            bar_post(2 + c);                       // publish xw chunk c
        }

        // ============ Phase C: sig scan, 8 chunks of 64 (warps 0-7) ========
        int a  = tid >> 4;
        int bb = tid & 15;

        float S1h = 0.f, S2 = 0.f;                 // S1h = S1/2 (exact scaling)
        u64t S3p[8];
#pragma unroll
        for (int j = 0; j < 8; j++) S3p[j] = 0ull;

        for (int k = 0; k < 8; k++) {
            bar_wait(6 + k);                       // HW-parked until chunk ready
            int tend = (k < 7) ? (k + 1) * 64 : NT;

#pragma unroll 2
            for (int t = k * 64; t < tend; t++) {
                const float* dr = ds + t * H;
                ulonglong2 p0 = *reinterpret_cast<const ulonglong2*>(dr);
                ulonglong2 p1 = *reinterpret_cast<const ulonglong2*>(dr + 4);
                ulonglong2 p2 = *reinterpret_cast<const ulonglong2*>(dr + 8);
                ulonglong2 p3 = *reinterpret_cast<const ulonglong2*>(dr + 12);
                float da = dr[a];
                float db = dr[bb];

                float m1   = da * db;
                float db2  = db + db;
                float coef = fmaf(S1h, db, fmaf(m1, (1.f / 6.f), S2));
                u64t cp = pack2_(coef, coef);

                S3p[0] = ffma2_(cp, p0.x, S3p[0]);
                S3p[1] = ffma2_(cp, p0.y, S3p[1]);
                S3p[2] = ffma2_(cp, p1.x, S3p[2]);
                S3p[3] = ffma2_(cp, p1.y, S3p[3]);
                S3p[4] = ffma2_(cp, p2.x, S3p[4]);
                S3p[5] = ffma2_(cp, p2.y, S3p[5]);
                S3p[6] = ffma2_(cp, p3.x, S3p[6]);
                S3p[7] = ffma2_(cp, p3.y, S3p[7]);

                S2  = fmaf(S1h, db2, fmaf(0.5f, m1, S2));
                S1h = fmaf(0.5f, da, S1h);
            }
        }

        // ---- fused FC ----
        float S3[16];
#pragma unroll
        for (int j = 0; j < 8; j++) unpack2_(S3p[j], S3[2 * j], S3[2 * j + 1]);
        float S1 = S1h + S1h;

        float part[O];
#pragma unroll
        for (int o = 0; o < O; o++) {
            const float* wr = fcw + (size_t)o * SIGD;
            float acc = S2 * __ldg(wr + H + tid);              // level-2 term
            if (bb == 0) acc = fmaf(S1, __ldg(wr + a), acc);   // level-1 term
            const float4* w4 = reinterpret_cast<const float4*>(wr + H + H * H + tid * 16);
#pragma unroll
            for (int j = 0; j < 4; j++) {
                float4 w = __ldg(w4 + j);
                acc = fmaf(S3[4 * j + 0], w.x, acc);
                acc = fmaf(S3[4 * j + 1], w.y, acc);
                acc = fmaf(S3[4 * j + 2], w.z, acc);
                acc = fmaf(S3[4 * j + 3], w.w, acc);
            }
            part[o] = acc;
        }

#pragma unroll
        for (int off = 16; off > 0; off >>= 1)
#pragma unroll
            for (int o = 0; o < O; o++)
                part[o] += __shfl_down_sync(0xffffffffu, part[o], off);
        if (lane == 0)
#pragma unroll
            for (int o = 0; o < O; o++) red[warp][o] = part[o];
    } else {
        // ============ Phase B: LSTM (warp 8) ===============================
        // lane l: rows l (i or f, x0.5) and l+32 (g unscaled / o x0.5)
        float sc1 = (lane < 16) ? 1.0f : 0.5f;
        float w0[H], w1[H];
#pragma unroll
        for (int j = 0; j < H; j++) {
            w0[j] = 0.5f * __ldg(Whh + lane * H + j);
            w1[j] = sc1  * __ldg(Whh + (lane + 32) * H + j);
        }
        float h[H];
#pragma unroll
        for (int j = 0; j < H; j++) h[j] = 0.f;
        float c = 0.f, hprev = 0.f;

        const float* xp = xwb + lane;

        bar_wait(2);                               // xw chunk 0 ready

        float bx0[4], bx1[4];
#pragma unroll
        for (int k = 0; k < 4; k++) { bx0[k] = xp[k * G]; bx1[k] = xp[k * G + 32]; }

#pragma unroll 4
        for (int t = 0; t < L; t++) {
            if ((t & 63) == 0 && t) {
                __threadfence_block();
                bar_post(5 + (t >> 6));            // sig chunk t/64-1 (ids 6..12)
                if ((t & 127) == 64 && t < 448)
                    bar_wait(3 + (t >> 7));        // xw chunk t/128+1 (ids 3..5)
            }

            int slot = t & 3;
            float a0 = bx0[slot], a1 = bx1[slot];
            if (t + 4 < L) { bx0[slot] = xp[(t + 4) * G]; bx1[slot] = xp[(t + 4) * G + 32]; }

            float q0 = 0.f, q1 = 0.f;
#pragma unroll
            for (int j = 0; j < 8; j++) {
                a0 = fmaf(h[j],     w0[j],     a0);
                q0 = fmaf(h[j + 8], w0[j + 8], q0);
                a1 = fmaf(h[j],     w1[j],     a1);
                q1 = fmaf(h[j + 8], w1[j + 8], q1);
            }
            a0 += q0; a1 += q1;
            // a0 = (i or f preact)/2 ; a1 = g preact (<16) or (o preact)/2 (>=16)

            float s0   = tanh_hw(a0);
            float sig0 = fmaf(s0, 0.5f, 0.5f);     // si (<16) / sf (>=16)
            float t1   = tanh_hw(a1);              // tg (<16) / tanh(o/2) (>=16)
            float soq  = fmaf(t1, 0.5f, 0.5f);     // so (valid on lanes>=16)

            float sf = __shfl_down_sync(0xffffffffu, sig0, 16);
            float so = __shfl_down_sync(0xffffffffu, soq, 16);

            c = fmaf(sf, c, sig0 * t1);            // lanes<16 valid
            float hn = so * tanh_hw(c);

            int buf = t & 1;
            if (lane < H) {
                hsm[buf][lane] = hn;
                if (t) ds[(t - 1) * H + lane] = hn - hprev;
                hprev = hn;
            }
            __syncwarp();
#pragma unroll
            for (int j = 0; j < H; j += 4) {
                float4 v = *reinterpret_cast<const float4*>(&hsm[buf][j]);
                h[j] = v.x; h[j + 1] = v.y; h[j + 2] = v.z; h[j + 3] = v.w;
            }
        }
        __threadfence_block();
        bar_post(13);                              // sig chunk 7 (448..510)
    }

    __syncthreads();                               // all 9 warps (barrier 0)
    if (tid < O) {
        float v = fcb[tid];
#pragma unroll
        for (int w = 0; w < 8; w++) v += red[w][tid];
        out[batch * O + tid] = v;
    }
}

// ---------------------------------------------------------------------------
extern "C" void kernel_launch(void* const* d_in, const int* in_sizes, int n_in,
                              void* d_out, int out_size) {
    const float* X   = (const float*)d_in[0];
    const float* Wih = (const float*)d_in[1];
    const float* Whh = (const float*)d_in[2];
    const float* bih = (const float*)d_in[3];
    const float* bhh = (const float*)d_in[4];
    const float* fcw = (const float*)d_in[5];
    const float* fcb = (const float*)d_in[6];
    float* out = (float*)d_out;

    fused_kernel<<<B, 288>>>(X, Wih, Whh, bih, bhh, fcw, fcb, out);
}